// round 3
// baseline (speedup 1.0000x reference)
#include <cuda_runtime.h>

// ---------------------------------------------------------------------------
// TensorCircuit forward, linear-domain reformulation.
//
// Reference (log domain):
//   input:  nm[i,b] = log_softmax(in_logits[i])[x[b, i/32]]
//   prod l: em[e,b] = nm[p0,b] + nm[p1,b]
//   sum  l: new[s,b] = logsumexp_c( em[cids[s,c],b] + log_softmax(w[s])[c] )
//
// Linear domain:
//   lin_in = softmax probs;  prod -> product;  sum -> weighted dot with
//   softmax(w). Per-batch-column max renormalization after each sum layer
//   keeps values in (0,1]; root = log(root_raw) + 8*log m1 + 4*log m2 + 2*log m3.
// ---------------------------------------------------------------------------

#define BATCH 1024
#define B4    256       // BATCH / 4 (float4 lanes)
#define NV    256
#define NK    64
#define NM    32
#define NN0   8192

// Arena offsets in floats (static device scratch; no allocations).
#define P_OFF    0u
#define LIN0_OFF (P_OFF + (unsigned)(NN0 * NK))            // softmax table: 512K
#define EM_OFF   (LIN0_OFF + (unsigned)(NN0 * BATCH))      // lin input:  8.39M
#define S1_OFF   (EM_OFF + 8192u * BATCH)                  // em scratch: 8.39M
#define S2_OFF   (S1_OFF + 4096u * BATCH)
#define S3_OFF   (S2_OFF + 2048u * BATCH)
#define M_OFF    (S3_OFF + 1024u * BATCH)
#define ARENA_SZ (M_OFF + 3u * BATCH)

__device__ float g_arena[ARENA_SZ];

// Zero the three per-batch column-max vectors (re-done every replay).
__global__ void __launch_bounds__(1024) k_zero() {
    g_arena[M_OFF + blockIdx.x * 1024 + threadIdx.x] = 0.0f;
}

// Softmax table: P[i,k] = softmax(in_logits[i])[k]. One warp per row.
__global__ void __launch_bounds__(256) k_softmax(const float* __restrict__ L) {
    int warp = threadIdx.x >> 5, lane = threadIdx.x & 31;
    int row = (blockIdx.x << 3) + warp;
    const float* lr = L + row * NK;
    float v0 = lr[lane], v1 = lr[lane + 32];
    float mx = fmaxf(v0, v1);
#pragma unroll
    for (int o = 16; o; o >>= 1) mx = fmaxf(mx, __shfl_xor_sync(0xffffffffu, mx, o));
    float e0 = __expf(v0 - mx), e1 = __expf(v1 - mx);
    float sm = e0 + e1;
#pragma unroll
    for (int o = 16; o; o >>= 1) sm += __shfl_xor_sync(0xffffffffu, sm, o);
    float inv = __frcp_rn(sm);
    g_arena[P_OFF + row * NK + lane]      = e0 * inv;
    g_arena[P_OFF + row * NK + lane + 32] = e1 * inv;
}

// Input gather: lin0[v*32+m, b] = P[v*32+m, x[b,v]].
// Block = (v, b-tile). One strided x read amortized over 32 output rows.
__global__ void __launch_bounds__(256) k_input(const int* __restrict__ x) {
    int v = blockIdx.x;
    int b = (blockIdx.y << 8) + threadIdx.x;
    int idx = x[b * NV + v];
    const float* Pb = g_arena + P_OFF + (v * NM) * NK + idx;
    float* o = g_arena + LIN0_OFF + (unsigned)(v * NM) * BATCH + b;
#pragma unroll
    for (int m = 0; m < NM; m++) o[m * BATCH] = Pb[m * NK];
}

// Prod layer: em[e,b] = prev[p0,b]*prev[p1,b] (* 1/m[b]^2 when renormalizing).
__global__ void __launch_bounds__(256) k_prod(unsigned em_off, unsigned prev_off,
                                              const int* __restrict__ pids, int start,
                                              unsigned m_off, int use_m) {
    int e = blockIdx.x, t = threadIdx.x;
    int p0 = __ldg(&pids[e * 2])     - start;
    int p1 = __ldg(&pids[e * 2 + 1]) - start;
    const float4* prev = (const float4*)(g_arena + prev_off);
    float4 a = prev[p0 * B4 + t];
    float4 b = prev[p1 * B4 + t];
    float4 r;
    r.x = a.x * b.x; r.y = a.y * b.y; r.z = a.z * b.z; r.w = a.w * b.w;
    if (use_m) {
        const float4* mm = (const float4*)(g_arena + m_off);
        float4 mv = mm[t];
        r.x *= __frcp_rn(mv.x * mv.x);
        r.y *= __frcp_rn(mv.y * mv.y);
        r.z *= __frcp_rn(mv.z * mv.z);
        r.w *= __frcp_rn(mv.w * mv.w);
    }
    ((float4*)(g_arena + em_off))[e * B4 + t] = r;
}

// Sum layer: out[s,b] = sum_c softmax(w[s])[c] * em[cids[s,c]-1, b].
// One block per sum node; 256 threads x float4 cover the batch.
__global__ void __launch_bounds__(256) k_sum(unsigned out_off, unsigned em_off,
                                             const int* __restrict__ cids,
                                             const float* __restrict__ w) {
    __shared__ float sw[32];
    __shared__ int   sc[32];
    int s = blockIdx.x, t = threadIdx.x;
    if (t < 32) {
        float wv = w[s * 32 + t];
        float mx = wv;
#pragma unroll
        for (int o = 16; o; o >>= 1) mx = fmaxf(mx, __shfl_xor_sync(0xffffffffu, mx, o));
        float e = __expf(wv - mx);
        float sm = e;
#pragma unroll
        for (int o = 16; o; o >>= 1) sm += __shfl_xor_sync(0xffffffffu, sm, o);
        sw[t] = e * __frcp_rn(sm);
        sc[t] = cids[s * 32 + t] - 1;
    }
    __syncthreads();
    const float4* em = (const float4*)(g_arena + em_off);
    float4 acc = make_float4(0.f, 0.f, 0.f, 0.f);
#pragma unroll
    for (int c = 0; c < 32; c++) {
        float wv = sw[c];
        float4 vv = em[sc[c] * B4 + t];
        acc.x = fmaf(wv, vv.x, acc.x);
        acc.y = fmaf(wv, vv.y, acc.y);
        acc.z = fmaf(wv, vv.z, acc.z);
        acc.w = fmaf(wv, vv.w, acc.w);
    }
    ((float4*)(g_arena + out_off))[s * B4 + t] = acc;
}

// Per-batch-column max over S rows. grid (4 b-tiles, 32 s-chunks) + atomicMax.
__global__ void __launch_bounds__(256) k_max(unsigned s_off, int rows_per,
                                             unsigned m_off) {
    int b = (blockIdx.x << 8) + threadIdx.x;
    const float* sr = g_arena + s_off + (unsigned)blockIdx.y * rows_per * BATCH + b;
    float loc = 0.0f;
#pragma unroll 8
    for (int i = 0; i < rows_per; i++) loc = fmaxf(loc, sr[i * BATCH]);
    atomicMax(reinterpret_cast<int*>(g_arena + m_off + b), __float_as_int(loc));
}

// Root: single sum node over layer-4 em, then undo the renormalizations in log.
__global__ void __launch_bounds__(256) k_root(float* __restrict__ out,
                                              const int* __restrict__ cids,
                                              const float* __restrict__ w) {
    __shared__ float sw[32];
    __shared__ int   sc[32];
    int t = threadIdx.x;
    if (t < 32) {
        float wv = w[t];
        float mx = wv;
#pragma unroll
        for (int o = 16; o; o >>= 1) mx = fmaxf(mx, __shfl_xor_sync(0xffffffffu, mx, o));
        float e = __expf(wv - mx);
        float sm = e;
#pragma unroll
        for (int o = 16; o; o >>= 1) sm += __shfl_xor_sync(0xffffffffu, sm, o);
        sw[t] = e * __frcp_rn(sm);
        sc[t] = cids[t] - 1;
    }
    __syncthreads();
    const float4* em = (const float4*)(g_arena + EM_OFF);
    float4 acc = make_float4(0.f, 0.f, 0.f, 0.f);
#pragma unroll
    for (int c = 0; c < 32; c++) {
        float wv = sw[c];
        float4 vv = em[sc[c] * B4 + t];
        acc.x = fmaf(wv, vv.x, acc.x);
        acc.y = fmaf(wv, vv.y, acc.y);
        acc.z = fmaf(wv, vv.z, acc.z);
        acc.w = fmaf(wv, vv.w, acc.w);
    }
    const float4* m1 = (const float4*)(g_arena + M_OFF);
    const float4* m2 = m1 + B4;
    const float4* m3 = m2 + B4;
    float4 a1 = m1[t], a2 = m2[t], a3 = m3[t];
    float4 o;
    o.x = logf(acc.x) + 8.f * logf(a1.x) + 4.f * logf(a2.x) + 2.f * logf(a3.x);
    o.y = logf(acc.y) + 8.f * logf(a1.y) + 4.f * logf(a2.y) + 2.f * logf(a3.y);
    o.z = logf(acc.z) + 8.f * logf(a1.z) + 4.f * logf(a2.z) + 2.f * logf(a3.z);
    o.w = logf(acc.w) + 8.f * logf(a1.w) + 4.f * logf(a2.w) + 2.f * logf(a3.w);
    ((float4*)out)[t] = o;
}

extern "C" void kernel_launch(void* const* d_in, const int* in_sizes, int n_in,
                              void* d_out, int out_size) {
    const int*   x      = (const int*)d_in[0];
    const float* logits = (const float*)d_in[1];
    const float* w1     = (const float*)d_in[2];
    const float* w2     = (const float*)d_in[3];
    const float* w3     = (const float*)d_in[4];
    const float* w4     = (const float*)d_in[5];
    const int*   pids1  = (const int*)d_in[6];
    const int*   pids2  = (const int*)d_in[7];
    const int*   pids3  = (const int*)d_in[8];
    const int*   pids4  = (const int*)d_in[9];
    const int*   cids1  = (const int*)d_in[10];
    const int*   cids2  = (const int*)d_in[11];
    const int*   cids3  = (const int*)d_in[12];
    const int*   cids4  = (const int*)d_in[13];

    k_zero<<<3, 1024>>>();
    k_softmax<<<NN0 / 8, 256>>>(logits);
    k_input<<<dim3(NV, BATCH / 256), 256>>>(x);

    // Layer 1: prod from inputs (global ids start at 1), no renorm yet.
    k_prod<<<8192, 256>>>(EM_OFF, LIN0_OFF, pids1, 1, 0u, 0);
    k_sum<<<4096, 256>>>(S1_OFF, EM_OFF, cids1, w1);
    k_max<<<dim3(4, 32), 256>>>(S1_OFF, 4096 / 32, M_OFF);

    // Layer 2: prod from s1 (ids start 8193), renormalize by m1.
    k_prod<<<4096, 256>>>(EM_OFF, S1_OFF, pids2, 1 + 8192, M_OFF, 1);
    k_sum<<<2048, 256>>>(S2_OFF, EM_OFF, cids2, w2);
    k_max<<<dim3(4, 32), 256>>>(S2_OFF, 2048 / 32, M_OFF + BATCH);

    // Layer 3: prod from s2 (ids start 12289), renormalize by m2.
    k_prod<<<2048, 256>>>(EM_OFF, S2_OFF, pids3, 1 + 8192 + 4096, M_OFF + BATCH, 1);
    k_sum<<<1024, 256>>>(S3_OFF, EM_OFF, cids3, w3);
    k_max<<<dim3(4, 32), 256>>>(S3_OFF, 1024 / 32, M_OFF + 2 * BATCH);

    // Layer 4: prod from s3 (ids start 14337), renormalize by m3; root finalize.
    k_prod<<<1024, 256>>>(EM_OFF, S3_OFF, pids4, 1 + 8192 + 4096 + 2048,
                          M_OFF + 2 * BATCH, 1);
    k_root<<<1, 256>>>((float*)d_out, cids4, w4);
}

// round 5
// speedup vs baseline: 1.4225x; 1.4225x over previous
#include <cuda_runtime.h>
#include <cuda_bf16.h>

// ---------------------------------------------------------------------------
// TensorCircuit forward, linear domain, bf16 activation storage.
//   input:  lin0[i,b] = softmax(in_logits[i])[x[b, i/32]]         (bf16)
//   prod l: em[e,b]   = prev[p0,b]*prev[p1,b] (* 1/m^2 renorm)    (bf16)
//   sum  l: s[s,b]    = sum_c softmax(w[s])[c] * em[cid,b]        (bf16, fp32 acc)
//   renorm: per-batch-column max m_l after each sum layer
//   root   = log(root_raw) + 8*log m1 + 4*log m2 + 2*log m3       (fp32)
// ---------------------------------------------------------------------------

#define BATCH 1024
#define NV    256
#define NK    64
#define NM    32
#define NN0   8192

// bf16 arena (element offsets). All offsets are multiples of 1024 -> 16B aligned.
#define LIN0  0u
#define EMO   (8192u * 1024u)
#define S1O   (EMO + 8192u * 1024u)
#define S2O   (S1O + 4096u * 1024u)
#define S3O   (S2O + 2048u * 1024u)
#define BF_SZ (S3O + 1024u * 1024u)

__device__ __nv_bfloat16 g_bf[BF_SZ];
__device__ float g_P[NN0 * NK];     // input softmax table (fp32)
__device__ float g_m[3 * BATCH];    // per-column renorm maxes (fp32)

// --- bf16 bit-trick helpers -------------------------------------------------
__device__ __forceinline__ float lo_bf(unsigned u) { return __uint_as_float(u << 16); }
__device__ __forceinline__ float hi_bf(unsigned u) { return __uint_as_float(u & 0xffff0000u); }
__device__ __forceinline__ unsigned pack_bf2(float lo, float hi) {
    unsigned r;
    asm("cvt.rn.bf16x2.f32 %0, %1, %2;" : "=r"(r) : "f"(hi), "f"(lo));
    return r;
}

// Zero the three per-batch column-max vectors (re-done every replay).
__global__ void __launch_bounds__(1024) k_zero() {
    g_m[blockIdx.x * 1024 + threadIdx.x] = 0.0f;
}

// Softmax table: P[i,k] = softmax(in_logits[i])[k]. One warp per row.
__global__ void __launch_bounds__(256) k_softmax(const float* __restrict__ L) {
    int warp = threadIdx.x >> 5, lane = threadIdx.x & 31;
    int row = (blockIdx.x << 3) + warp;
    const float* lr = L + row * NK;
    float v0 = lr[lane], v1 = lr[lane + 32];
    float mx = fmaxf(v0, v1);
#pragma unroll
    for (int o = 16; o; o >>= 1) mx = fmaxf(mx, __shfl_xor_sync(0xffffffffu, mx, o));
    float e0 = __expf(v0 - mx), e1 = __expf(v1 - mx);
    float sm = e0 + e1;
#pragma unroll
    for (int o = 16; o; o >>= 1) sm += __shfl_xor_sync(0xffffffffu, sm, o);
    float inv = __frcp_rn(sm);
    g_P[row * NK + lane]      = e0 * inv;
    g_P[row * NK + lane + 32] = e1 * inv;
}

// Input gather: lin0[v*32+m, b] = P[v*32+m, x[b,v]]  (bf16 store).
__global__ void __launch_bounds__(256) k_input(const int* __restrict__ x) {
    int v = blockIdx.x;
    int b = (blockIdx.y << 8) + threadIdx.x;
    int idx = x[b * NV + v];
    const float* Pb = g_P + (v * NM) * NK + idx;
    __nv_bfloat16* o = g_bf + LIN0 + (unsigned)(v * NM) * BATCH + b;
#pragma unroll
    for (int m = 0; m < NM; m++) o[m * BATCH] = __float2bfloat16(Pb[m * NK]);
}

// Prod layer: em[e,b] = prev[p0,b]*prev[p1,b] (* 1/m^2 when renormalizing).
// 128 threads x 8 bf16 (uint4) per row.
__global__ void __launch_bounds__(128) k_prod(unsigned em_off, unsigned prev_off,
                                              const int* __restrict__ pids, int start,
                                              int m_idx) {
    int e = blockIdx.x, t = threadIdx.x;
    int p0 = __ldg(&pids[e * 2])     - start;
    int p1 = __ldg(&pids[e * 2 + 1]) - start;
    const uint4* prev = (const uint4*)(g_bf + prev_off);
    uint4 ua = prev[p0 * 128 + t];
    uint4 ub = prev[p1 * 128 + t];
    float r[8];
    r[0] = lo_bf(ua.x) * lo_bf(ub.x);  r[1] = hi_bf(ua.x) * hi_bf(ub.x);
    r[2] = lo_bf(ua.y) * lo_bf(ub.y);  r[3] = hi_bf(ua.y) * hi_bf(ub.y);
    r[4] = lo_bf(ua.z) * lo_bf(ub.z);  r[5] = hi_bf(ua.z) * hi_bf(ub.z);
    r[6] = lo_bf(ua.w) * lo_bf(ub.w);  r[7] = hi_bf(ua.w) * hi_bf(ub.w);
    if (m_idx >= 0) {
        const float4* mm = (const float4*)(g_m + m_idx * BATCH);
        float4 m0 = mm[2 * t], m1 = mm[2 * t + 1];
        r[0] *= __frcp_rn(m0.x * m0.x);  r[1] *= __frcp_rn(m0.y * m0.y);
        r[2] *= __frcp_rn(m0.z * m0.z);  r[3] *= __frcp_rn(m0.w * m0.w);
        r[4] *= __frcp_rn(m1.x * m1.x);  r[5] *= __frcp_rn(m1.y * m1.y);
        r[6] *= __frcp_rn(m1.z * m1.z);  r[7] *= __frcp_rn(m1.w * m1.w);
    }
    uint4 o;
    o.x = pack_bf2(r[0], r[1]);  o.y = pack_bf2(r[2], r[3]);
    o.z = pack_bf2(r[4], r[5]);  o.w = pack_bf2(r[6], r[7]);
    ((uint4*)(g_bf + em_off))[e * 128 + t] = o;
}

// Sum layer: out[s,b] = sum_c softmax(w[s])[c] * em[cids[s,c]-1, b].
// One block per sum node; 128 threads x 8 bf16 cover the batch. fp32 acc.
__global__ void __launch_bounds__(128) k_sum(unsigned out_off, unsigned em_off,
                                             const int* __restrict__ cids,
                                             const float* __restrict__ w) {
    __shared__ float sw[32];
    __shared__ int   sc[32];
    int s = blockIdx.x, t = threadIdx.x;
    if (t < 32) {
        float wv = w[s * 32 + t];
        float mx = wv;
#pragma unroll
        for (int o = 16; o; o >>= 1) mx = fmaxf(mx, __shfl_xor_sync(0xffffffffu, mx, o));
        float e = __expf(wv - mx);
        float sm = e;
#pragma unroll
        for (int o = 16; o; o >>= 1) sm += __shfl_xor_sync(0xffffffffu, sm, o);
        sw[t] = e * __frcp_rn(sm);
        sc[t] = cids[s * 32 + t] - 1;
    }
    __syncthreads();
    const uint4* em = (const uint4*)(g_bf + em_off);
    float a0 = 0.f, a1 = 0.f, a2 = 0.f, a3 = 0.f;
    float a4 = 0.f, a5 = 0.f, a6 = 0.f, a7 = 0.f;
#pragma unroll
    for (int c = 0; c < 32; c++) {
        uint4 u = em[sc[c] * 128 + t];
        float wv = sw[c];
        a0 = fmaf(wv, lo_bf(u.x), a0);  a1 = fmaf(wv, hi_bf(u.x), a1);
        a2 = fmaf(wv, lo_bf(u.y), a2);  a3 = fmaf(wv, hi_bf(u.y), a3);
        a4 = fmaf(wv, lo_bf(u.z), a4);  a5 = fmaf(wv, hi_bf(u.z), a5);
        a6 = fmaf(wv, lo_bf(u.w), a6);  a7 = fmaf(wv, hi_bf(u.w), a7);
    }
    uint4 o;
    o.x = pack_bf2(a0, a1);  o.y = pack_bf2(a2, a3);
    o.z = pack_bf2(a4, a5);  o.w = pack_bf2(a6, a7);
    ((uint4*)(g_bf + out_off))[s * 128 + t] = o;
}

// Per-batch-column max over S rows (bf16 source). grid (4 b-tiles, 32 s-chunks).
__global__ void __launch_bounds__(256) k_max(unsigned s_off, int rows_per, int m_idx) {
    int b = (blockIdx.x << 8) + threadIdx.x;
    const unsigned short* sr =
        (const unsigned short*)g_bf + s_off + (unsigned)blockIdx.y * rows_per * BATCH + b;
    float loc = 0.0f;
#pragma unroll 8
    for (int i = 0; i < rows_per; i++)
        loc = fmaxf(loc, __uint_as_float((unsigned)sr[i * BATCH] << 16));
    atomicMax(reinterpret_cast<int*>(g_m + m_idx * BATCH + b), __float_as_int(loc));
}

// Root: single sum node over layer-4 em, undo the renormalizations in log.
__global__ void __launch_bounds__(256) k_root(float* __restrict__ out,
                                              const int* __restrict__ cids,
                                              const float* __restrict__ w) {
    __shared__ float sw[32];
    __shared__ int   sc[32];
    int t = threadIdx.x;
    if (t < 32) {
        float wv = w[t];
        float mx = wv;
#pragma unroll
        for (int o = 16; o; o >>= 1) mx = fmaxf(mx, __shfl_xor_sync(0xffffffffu, mx, o));
        float e = __expf(wv - mx);
        float sm = e;
#pragma unroll
        for (int o = 16; o; o >>= 1) sm += __shfl_xor_sync(0xffffffffu, sm, o);
        sw[t] = e * __frcp_rn(sm);
        sc[t] = cids[t] - 1;
    }
    __syncthreads();
    const uint2* em = (const uint2*)(g_bf + EMO);
    float a0 = 0.f, a1 = 0.f, a2 = 0.f, a3 = 0.f;
#pragma unroll
    for (int c = 0; c < 32; c++) {
        uint2 u = em[sc[c] * 256 + t];
        float wv = sw[c];
        a0 = fmaf(wv, lo_bf(u.x), a0);  a1 = fmaf(wv, hi_bf(u.x), a1);
        a2 = fmaf(wv, lo_bf(u.y), a2);  a3 = fmaf(wv, hi_bf(u.y), a3);
    }
    const float4* m1 = (const float4*)g_m;
    const float4* m2 = (const float4*)(g_m + BATCH);
    const float4* m3 = (const float4*)(g_m + 2 * BATCH);
    float4 b1 = m1[t], b2 = m2[t], b3 = m3[t];
    float4 o;
    o.x = logf(a0) + 8.f * logf(b1.x) + 4.f * logf(b2.x) + 2.f * logf(b3.x);
    o.y = logf(a1) + 8.f * logf(b1.y) + 4.f * logf(b2.y) + 2.f * logf(b3.y);
    o.z = logf(a2) + 8.f * logf(b1.z) + 4.f * logf(b2.z) + 2.f * logf(b3.z);
    o.w = logf(a3) + 8.f * logf(b1.w) + 4.f * logf(b2.w) + 2.f * logf(b3.w);
    ((float4*)out)[t] = o;
}

extern "C" void kernel_launch(void* const* d_in, const int* in_sizes, int n_in,
                              void* d_out, int out_size) {
    const int*   x      = (const int*)d_in[0];
    const float* logits = (const float*)d_in[1];
    const float* w1     = (const float*)d_in[2];
    const float* w2     = (const float*)d_in[3];
    const float* w3     = (const float*)d_in[4];
    const float* w4     = (const float*)d_in[5];
    const int*   pids1  = (const int*)d_in[6];
    const int*   pids2  = (const int*)d_in[7];
    const int*   pids3  = (const int*)d_in[8];
    const int*   pids4  = (const int*)d_in[9];
    const int*   cids1  = (const int*)d_in[10];
    const int*   cids2  = (const int*)d_in[11];
    const int*   cids3  = (const int*)d_in[12];
    const int*   cids4  = (const int*)d_in[13];

    k_zero<<<3, 1024>>>();
    k_softmax<<<NN0 / 8, 256>>>(logits);
    k_input<<<dim3(NV, BATCH / 256), 256>>>(x);

    // Layer 1: prod from inputs (global ids start at 1), no renorm yet.
    k_prod<<<8192, 128>>>(EMO, LIN0, pids1, 1, -1);
    k_sum<<<4096, 128>>>(S1O, EMO, cids1, w1);
    k_max<<<dim3(4, 32), 256>>>(S1O, 4096 / 32, 0);

    // Layer 2: prod from s1 (ids start 8193), renormalize by m1.
    k_prod<<<4096, 128>>>(EMO, S1O, pids2, 1 + 8192, 0);
    k_sum<<<2048, 128>>>(S2O, EMO, cids2, w2);
    k_max<<<dim3(4, 32), 256>>>(S2O, 2048 / 32, 1);

    // Layer 3: prod from s2 (ids start 12289), renormalize by m2.
    k_prod<<<2048, 128>>>(EMO, S2O, pids3, 1 + 8192 + 4096, 1);
    k_sum<<<1024, 128>>>(S3O, EMO, cids3, w3);
    k_max<<<dim3(4, 32), 256>>>(S3O, 1024 / 32, 2);

    // Layer 4: prod from s3 (ids start 14337), renormalize by m3; root finalize.
    k_prod<<<1024, 128>>>(EMO, S3O, pids4, 1 + 8192 + 4096 + 2048, 2);
    k_root<<<1, 256>>>((float*)d_out, cids4, w4);
}

// round 8
// speedup vs baseline: 1.5092x; 1.0609x over previous
#include <cuda_runtime.h>
#include <cuda_bf16.h>

// ---------------------------------------------------------------------------
// TensorCircuit forward, linear domain, bf16 activation storage.
//   input:  lin0[i,b] = softmax(in_logits[i])[x[b, i/32]]         (bf16)
//   prod l: em[e,b]   = prev[p0,b]*prev[p1,b] (* 1/m^2 renorm)    (bf16)
//   sum  l: s[s,b]    = sum_c softmax(w[s])[c] * em[cid,b]        (bf16, fp32 acc)
//   renorm: per-batch-column max AFTER s2 and s3 only (s1 range is safe in bf16)
//   root   = log(root_raw) + 4*log m2 + 2*log m3                  (fp32)
// ---------------------------------------------------------------------------

#define BATCH 1024
#define NV    256
#define NK    64
#define NM    32
#define NN0   8192
#define EPB   16          // elements per k_prod block

// bf16 arena (element offsets). All offsets are multiples of 1024 -> 16B aligned.
#define LIN0  0u
#define EMO   (8192u * 1024u)
#define S1O   (EMO + 8192u * 1024u)
#define S2O   (S1O + 4096u * 1024u)
#define S3O   (S2O + 2048u * 1024u)
#define BF_SZ (S3O + 1024u * 1024u)

__device__ __nv_bfloat16 g_bf[BF_SZ];
__device__ float g_P[NN0 * NK];     // input softmax table (fp32)
__device__ float g_m[2 * BATCH];    // per-column renorm maxes: m2, m3 (fp32)

// --- bf16 bit-trick helpers -------------------------------------------------
__device__ __forceinline__ float lo_bf(unsigned u) { return __uint_as_float(u << 16); }
__device__ __forceinline__ float hi_bf(unsigned u) { return __uint_as_float(u & 0xffff0000u); }
__device__ __forceinline__ unsigned pack_bf2(float lo, float hi) {
    unsigned r;
    asm("cvt.rn.bf16x2.f32 %0, %1, %2;" : "=r"(r) : "f"(hi), "f"(lo));
    return r;
}

// Softmax table: P[i,k] = softmax(in_logits[i])[k]. One warp per row.
// Blocks 0..7 additionally zero the renorm-max vectors (fused k_zero).
__global__ void __launch_bounds__(256) k_softmax(const float* __restrict__ L) {
    unsigned gz = blockIdx.x * 256 + threadIdx.x;
    if (gz < 2u * BATCH) g_m[gz] = 0.0f;
    int warp = threadIdx.x >> 5, lane = threadIdx.x & 31;
    int row = (blockIdx.x << 3) + warp;
    const float* lr = L + row * NK;
    float v0 = lr[lane], v1 = lr[lane + 32];
    float mx = fmaxf(v0, v1);
#pragma unroll
    for (int o = 16; o; o >>= 1) mx = fmaxf(mx, __shfl_xor_sync(0xffffffffu, mx, o));
    float e0 = __expf(v0 - mx), e1 = __expf(v1 - mx);
    float sm = e0 + e1;
#pragma unroll
    for (int o = 16; o; o >>= 1) sm += __shfl_xor_sync(0xffffffffu, sm, o);
    float inv = __frcp_rn(sm);
    g_P[row * NK + lane]      = e0 * inv;
    g_P[row * NK + lane + 32] = e1 * inv;
}

// Input gather: lin0[v*32+m, b] = P[v*32+m, x[b,v]]  (bf16 store).
__global__ void __launch_bounds__(256) k_input(const int* __restrict__ x) {
    int v = blockIdx.x;
    int b = (blockIdx.y << 8) + threadIdx.x;
    int idx = x[b * NV + v];
    const float* Pb = g_P + (v * NM) * NK + idx;
    __nv_bfloat16* o = g_bf + LIN0 + (unsigned)(v * NM) * BATCH + b;
#pragma unroll
    for (int m = 0; m < NM; m++) o[m * BATCH] = __float2bfloat16(Pb[m * NK]);
}

// Prod layer: em[e,b] = prev[p0,b]*prev[p1,b] (* 1/m^2 when renormalizing).
// 256 threads; each half-block covers one 2KB row; EPB elements per block.
// Renorm factors are loop-invariant per thread -> hoisted into registers.
__global__ void __launch_bounds__(256) k_prod(unsigned em_off, unsigned prev_off,
                                              const int* __restrict__ pids, int start,
                                              int m_idx) {
    __shared__ int sp[EPB * 2];
    int tid = threadIdx.x;
    if (tid < EPB * 2) sp[tid] = __ldg(&pids[blockIdx.x * EPB * 2 + tid]) - start;
    int half = tid >> 7, t = tid & 127;
    float inv[8];
    const bool use_m = (m_idx >= 0);
    if (use_m) {
        const float4* mm = (const float4*)(g_m + m_idx * BATCH);
        float4 m0 = mm[2 * t], m1 = mm[2 * t + 1];
        inv[0] = __frcp_rn(m0.x * m0.x);  inv[1] = __frcp_rn(m0.y * m0.y);
        inv[2] = __frcp_rn(m0.z * m0.z);  inv[3] = __frcp_rn(m0.w * m0.w);
        inv[4] = __frcp_rn(m1.x * m1.x);  inv[5] = __frcp_rn(m1.y * m1.y);
        inv[6] = __frcp_rn(m1.z * m1.z);  inv[7] = __frcp_rn(m1.w * m1.w);
    }
    __syncthreads();
    const uint4* prev = (const uint4*)(g_bf + prev_off);
    uint4* out = (uint4*)(g_bf + em_off);
    unsigned ebase = blockIdx.x * EPB;
#pragma unroll
    for (int ii = 0; ii < EPB / 2; ii++) {
        int i = 2 * ii + half;
        int p0 = sp[2 * i], p1 = sp[2 * i + 1];
        uint4 ua = prev[(unsigned)p0 * 128 + t];
        uint4 ub = prev[(unsigned)p1 * 128 + t];
        float r[8];
        r[0] = lo_bf(ua.x) * lo_bf(ub.x);  r[1] = hi_bf(ua.x) * hi_bf(ub.x);
        r[2] = lo_bf(ua.y) * lo_bf(ub.y);  r[3] = hi_bf(ua.y) * hi_bf(ub.y);
        r[4] = lo_bf(ua.z) * lo_bf(ub.z);  r[5] = hi_bf(ua.z) * hi_bf(ub.z);
        r[6] = lo_bf(ua.w) * lo_bf(ub.w);  r[7] = hi_bf(ua.w) * hi_bf(ub.w);
        if (use_m) {
#pragma unroll
            for (int j = 0; j < 8; j++) r[j] *= inv[j];
        }
        uint4 o;
        o.x = pack_bf2(r[0], r[1]);  o.y = pack_bf2(r[2], r[3]);
        o.z = pack_bf2(r[4], r[5]);  o.w = pack_bf2(r[6], r[7]);
        out[(ebase + i) * 128 + t] = o;
    }
}

// Sum layer: out[s,b] = sum_c softmax(w[s])[c] * em[cids[s,c]-1, b].
// One block per sum node; 128 threads x 8 bf16 cover the batch. fp32 acc.
__global__ void __launch_bounds__(128) k_sum(unsigned out_off, unsigned em_off,
                                             const int* __restrict__ cids,
                                             const float* __restrict__ w) {
    __shared__ float sw[32];
    __shared__ int   sc[32];
    int s = blockIdx.x, t = threadIdx.x;
    if (t < 32) {
        float wv = w[s * 32 + t];
        float mx = wv;
#pragma unroll
        for (int o = 16; o; o >>= 1) mx = fmaxf(mx, __shfl_xor_sync(0xffffffffu, mx, o));
        float e = __expf(wv - mx);
        float sm = e;
#pragma unroll
        for (int o = 16; o; o >>= 1) sm += __shfl_xor_sync(0xffffffffu, sm, o);
        sw[t] = e * __frcp_rn(sm);
        sc[t] = cids[s * 32 + t] - 1;
    }
    __syncthreads();
    const uint4* em = (const uint4*)(g_bf + em_off);
    float a0 = 0.f, a1 = 0.f, a2 = 0.f, a3 = 0.f;
    float a4 = 0.f, a5 = 0.f, a6 = 0.f, a7 = 0.f;
#pragma unroll
    for (int c = 0; c < 32; c++) {
        uint4 u = em[sc[c] * 128 + t];
        float wv = sw[c];
        a0 = fmaf(wv, lo_bf(u.x), a0);  a1 = fmaf(wv, hi_bf(u.x), a1);
        a2 = fmaf(wv, lo_bf(u.y), a2);  a3 = fmaf(wv, hi_bf(u.y), a3);
        a4 = fmaf(wv, lo_bf(u.z), a4);  a5 = fmaf(wv, hi_bf(u.z), a5);
        a6 = fmaf(wv, lo_bf(u.w), a6);  a7 = fmaf(wv, hi_bf(u.w), a7);
    }
    uint4 o;
    o.x = pack_bf2(a0, a1);  o.y = pack_bf2(a2, a3);
    o.z = pack_bf2(a4, a5);  o.w = pack_bf2(a6, a7);
    ((uint4*)(g_bf + out_off))[s * 128 + t] = o;
}

// Per-batch-column max over S rows (bf16 source). grid (4 b-tiles, 32 s-chunks).
__global__ void __launch_bounds__(256) k_max(unsigned s_off, int rows_per, int m_idx) {
    int b = (blockIdx.x << 8) + threadIdx.x;
    const unsigned short* sr =
        (const unsigned short*)g_bf + s_off + (unsigned)blockIdx.y * rows_per * BATCH + b;
    float loc = 0.0f;
#pragma unroll 8
    for (int i = 0; i < rows_per; i++)
        loc = fmaxf(loc, __uint_as_float((unsigned)sr[i * BATCH] << 16));
    atomicMax(reinterpret_cast<int*>(g_m + m_idx * BATCH + b), __float_as_int(loc));
}

// Root: single sum node over layer-4 em, undo the renormalizations in log.
__global__ void __launch_bounds__(256) k_root(float* __restrict__ out,
                                              const int* __restrict__ cids,
                                              const float* __restrict__ w) {
    __shared__ float sw[32];
    __shared__ int   sc[32];
    int t = threadIdx.x;
    if (t < 32) {
        float wv = w[t];
        float mx = wv;
#pragma unroll
        for (int o = 16; o; o >>= 1) mx = fmaxf(mx, __shfl_xor_sync(0xffffffffu, mx, o));
        float e = __expf(wv - mx);
        float sm = e;
#pragma unroll
        for (int o = 16; o; o >>= 1) sm += __shfl_xor_sync(0xffffffffu, sm, o);
        sw[t] = e * __frcp_rn(sm);
        sc[t] = cids[t] - 1;
    }
    __syncthreads();
    const uint2* em = (const uint2*)(g_bf + EMO);
    float a0 = 0.f, a1 = 0.f, a2 = 0.f, a3 = 0.f;
#pragma unroll
    for (int c = 0; c < 32; c++) {
        uint2 u = em[sc[c] * 256 + t];
        float wv = sw[c];
        a0 = fmaf(wv, lo_bf(u.x), a0);  a1 = fmaf(wv, hi_bf(u.x), a1);
        a2 = fmaf(wv, lo_bf(u.y), a2);  a3 = fmaf(wv, hi_bf(u.y), a3);
    }
    const float4* m2 = (const float4*)g_m;
    const float4* m3 = (const float4*)(g_m + BATCH);
    float4 b2 = m2[t], b3 = m3[t];
    float4 o;
    o.x = logf(a0) + 4.f * logf(b2.x) + 2.f * logf(b3.x);
    o.y = logf(a1) + 4.f * logf(b2.y) + 2.f * logf(b3.y);
    o.z = logf(a2) + 4.f * logf(b2.z) + 2.f * logf(b3.z);
    o.w = logf(a3) + 4.f * logf(b2.w) + 2.f * logf(b3.w);
    ((float4*)out)[t] = o;
}

extern "C" void kernel_launch(void* const* d_in, const int* in_sizes, int n_in,
                              void* d_out, int out_size) {
    const int*   x      = (const int*)d_in[0];
    const float* logits = (const float*)d_in[1];
    const float* w1     = (const float*)d_in[2];
    const float* w2     = (const float*)d_in[3];
    const float* w3     = (const float*)d_in[4];
    const float* w4     = (const float*)d_in[5];
    const int*   pids1  = (const int*)d_in[6];
    const int*   pids2  = (const int*)d_in[7];
    const int*   pids3  = (const int*)d_in[8];
    const int*   pids4  = (const int*)d_in[9];
    const int*   cids1  = (const int*)d_in[10];
    const int*   cids2  = (const int*)d_in[11];
    const int*   cids3  = (const int*)d_in[12];
    const int*   cids4  = (const int*)d_in[13];

    k_softmax<<<NN0 / 8, 256>>>(logits);       // also zeros g_m
    k_input<<<dim3(NV, BATCH / 256), 256>>>(x);

    // Layer 1: prod from inputs (global ids start at 1). No renorm needed.
    k_prod<<<8192 / EPB, 256>>>(EMO, LIN0, pids1, 1, -1);
    k_sum<<<4096, 128>>>(S1O, EMO, cids1, w1);

    // Layer 2: prod from s1 (ids start 8193). s1 range safe in bf16 -> no renorm.
    k_prod<<<4096 / EPB, 256>>>(EMO, S1O, pids2, 1 + 8192, -1);
    k_sum<<<2048, 128>>>(S2O, EMO, cids2, w2);
    k_max<<<dim3(4, 32), 256>>>(S2O, 2048 / 32, 0);

    // Layer 3: prod from s2 (ids start 12289), renormalize by m2.
    k_prod<<<2048 / EPB, 256>>>(EMO, S2O, pids3, 1 + 8192 + 4096, 0);
    k_sum<<<1024, 128>>>(S3O, EMO, cids3, w3);
    k_max<<<dim3(4, 32), 256>>>(S3O, 1024 / 32, 1);

    // Layer 4: prod from s3 (ids start 14337), renormalize by m3; root finalize.
    k_prod<<<1024 / EPB, 256>>>(EMO, S3O, pids4, 1 + 8192 + 4096 + 2048, 1);
    k_root<<<1, 256>>>((float*)d_out, cids4, w4);
}

// round 9
// speedup vs baseline: 1.7232x; 1.1418x over previous
#include <cuda_runtime.h>
#include <cuda_bf16.h>

// ---------------------------------------------------------------------------
// TensorCircuit forward, linear domain, bf16 activation storage.
//   input:  lin0[i,b] = softmax(in_logits[i])[x[b, i/32]]         (bf16)
//   prod l: em[e,b]   = prev[p0,b]*prev[p1,b] (/ m2^2 at layer 3) (bf16)
//   sum  l: s[s,b]    = sum_c softmax(w[s])[c] * em[cid,b]        (bf16, fp32 acc)
//   renorm: single per-batch-column max m2 after s2 (only squaring that risks
//           bf16 underflow before the root)
//   layer4 prod+sum collapsed into k_root: only 32 of 1024 elements are used.
//   root   = log( sum_c w4_c * s3[p0_c]*s3[p1_c] ) + 4*log m2     (fp32)
// ---------------------------------------------------------------------------

#define BATCH 1024
#define NV    256
#define NK    64
#define NM    32
#define NN0   8192
#define EPB   16          // elements per k_prod block

// bf16 arena (element offsets). All offsets are multiples of 1024 -> 16B aligned.
#define LIN0  0u
#define EMO   (8192u * 1024u)
#define S1O   (EMO + 8192u * 1024u)
#define S2O   (S1O + 4096u * 1024u)
#define S3O   (S2O + 2048u * 1024u)
#define BF_SZ (S3O + 1024u * 1024u)

__device__ __nv_bfloat16 g_bf[BF_SZ];
__device__ float g_m[BATCH];        // per-column renorm max m2 (fp32)

// --- bf16 bit-trick helpers -------------------------------------------------
__device__ __forceinline__ float lo_bf(unsigned u) { return __uint_as_float(u << 16); }
__device__ __forceinline__ float hi_bf(unsigned u) { return __uint_as_float(u & 0xffff0000u); }
__device__ __forceinline__ unsigned pack_bf2(float lo, float hi) {
    unsigned r;
    asm("cvt.rn.bf16x2.f32 %0, %1, %2;" : "=r"(r) : "f"(hi), "f"(lo));
    return r;
}

// Fused input layer: per-variable block computes the 32-row softmax tile in
// smem (transposed, padded -> conflict-free random gather), then writes
// lin0[v*32+m, b] = P[x[b,v]][m] for all 1024 batch columns. Blocks 0..3 also
// zero the m2 vector.
__global__ void __launch_bounds__(256) k_inp(const float* __restrict__ L,
                                             const int* __restrict__ x) {
    __shared__ float Pt[NK][NM + 1];   // transposed softmax tile, padded
    int v = blockIdx.x;
    if (v < 4) g_m[v * 256 + threadIdx.x] = 0.0f;
    int warp = threadIdx.x >> 5, lane = threadIdx.x & 31;
    // 8 warps x 4 rows each: softmax over 64 logits per row.
#pragma unroll
    for (int i = 0; i < 4; i++) {
        int m = warp * 4 + i;
        const float* lr = L + (v * NM + m) * NK;
        float v0 = lr[lane], v1 = lr[lane + 32];
        float mx = fmaxf(v0, v1);
#pragma unroll
        for (int o = 16; o; o >>= 1) mx = fmaxf(mx, __shfl_xor_sync(0xffffffffu, mx, o));
        float e0 = __expf(v0 - mx), e1 = __expf(v1 - mx);
        float sm = e0 + e1;
#pragma unroll
        for (int o = 16; o; o >>= 1) sm += __shfl_xor_sync(0xffffffffu, sm, o);
        float inv = __frcp_rn(sm);
        Pt[lane][m]      = e0 * inv;
        Pt[lane + 32][m] = e1 * inv;
    }
    __syncthreads();
#pragma unroll
    for (int j = 0; j < 4; j++) {
        int b = threadIdx.x + j * 256;
        int idx = x[b * NV + v];
        __nv_bfloat16* o = g_bf + LIN0 + (unsigned)(v * NM) * BATCH + b;
#pragma unroll
        for (int m = 0; m < NM; m++) o[m * BATCH] = __float2bfloat16(Pt[idx][m]);
    }
}

// Prod layer: em[e,b] = prev[p0,b]*prev[p1,b] (* 1/m2^2 when renormalizing).
// 256 threads; each half-block covers one 2KB row; EPB elements per block.
__global__ void __launch_bounds__(256) k_prod(unsigned em_off, unsigned prev_off,
                                              const int* __restrict__ pids, int start,
                                              int use_m) {
    __shared__ int sp[EPB * 2];
    int tid = threadIdx.x;
    if (tid < EPB * 2) sp[tid] = __ldg(&pids[blockIdx.x * EPB * 2 + tid]) - start;
    int half = tid >> 7, t = tid & 127;
    float inv[8];
    if (use_m) {
        const float4* mm = (const float4*)g_m;
        float4 m0 = mm[2 * t], m1 = mm[2 * t + 1];
        inv[0] = __frcp_rn(m0.x * m0.x);  inv[1] = __frcp_rn(m0.y * m0.y);
        inv[2] = __frcp_rn(m0.z * m0.z);  inv[3] = __frcp_rn(m0.w * m0.w);
        inv[4] = __frcp_rn(m1.x * m1.x);  inv[5] = __frcp_rn(m1.y * m1.y);
        inv[6] = __frcp_rn(m1.z * m1.z);  inv[7] = __frcp_rn(m1.w * m1.w);
    }
    __syncthreads();
    const uint4* prev = (const uint4*)(g_bf + prev_off);
    uint4* out = (uint4*)(g_bf + em_off);
    unsigned ebase = blockIdx.x * EPB;
#pragma unroll
    for (int ii = 0; ii < EPB / 2; ii++) {
        int i = 2 * ii + half;
        int p0 = sp[2 * i], p1 = sp[2 * i + 1];
        uint4 ua = prev[(unsigned)p0 * 128 + t];
        uint4 ub = prev[(unsigned)p1 * 128 + t];
        float r[8];
        r[0] = lo_bf(ua.x) * lo_bf(ub.x);  r[1] = hi_bf(ua.x) * hi_bf(ub.x);
        r[2] = lo_bf(ua.y) * lo_bf(ub.y);  r[3] = hi_bf(ua.y) * hi_bf(ub.y);
        r[4] = lo_bf(ua.z) * lo_bf(ub.z);  r[5] = hi_bf(ua.z) * hi_bf(ub.z);
        r[6] = lo_bf(ua.w) * lo_bf(ub.w);  r[7] = hi_bf(ua.w) * hi_bf(ub.w);
        if (use_m) {
#pragma unroll
            for (int j = 0; j < 8; j++) r[j] *= inv[j];
        }
        uint4 o;
        o.x = pack_bf2(r[0], r[1]);  o.y = pack_bf2(r[2], r[3]);
        o.z = pack_bf2(r[4], r[5]);  o.w = pack_bf2(r[6], r[7]);
        out[(ebase + i) * 128 + t] = o;
    }
}

// Sum layer: out[s,b] = sum_c softmax(w[s])[c] * em[cids[s,c]-1, b].
// One block per sum node; 128 threads x 8 bf16 cover the batch. fp32 acc.
// Weight + premultiplied byte-offset packed into one smem uint2 per child.
__global__ void __launch_bounds__(128) k_sum(unsigned out_off, unsigned em_off,
                                             const int* __restrict__ cids,
                                             const float* __restrict__ w) {
    __shared__ uint2 swc[32];
    int s = blockIdx.x, t = threadIdx.x;
    if (t < 32) {
        float wv = w[s * 32 + t];
        float mx = wv;
#pragma unroll
        for (int o = 16; o; o >>= 1) mx = fmaxf(mx, __shfl_xor_sync(0xffffffffu, mx, o));
        float e = __expf(wv - mx);
        float sm = e;
#pragma unroll
        for (int o = 16; o; o >>= 1) sm += __shfl_xor_sync(0xffffffffu, sm, o);
        unsigned off = (unsigned)(cids[s * 32 + t] - 1) * 2048u;  // byte offset of row
        swc[t] = make_uint2(__float_as_uint(e * __frcp_rn(sm)), off);
    }
    __syncthreads();
    const char* base = (const char*)(g_bf + em_off) + t * 16;
    float a0 = 0.f, a1 = 0.f, a2 = 0.f, a3 = 0.f;
    float a4 = 0.f, a5 = 0.f, a6 = 0.f, a7 = 0.f;
#pragma unroll
    for (int c = 0; c < 32; c++) {
        uint2 wc = swc[c];
        uint4 u = *(const uint4*)(base + wc.y);
        float wv = __uint_as_float(wc.x);
        a0 = fmaf(wv, lo_bf(u.x), a0);  a1 = fmaf(wv, hi_bf(u.x), a1);
        a2 = fmaf(wv, lo_bf(u.y), a2);  a3 = fmaf(wv, hi_bf(u.y), a3);
        a4 = fmaf(wv, lo_bf(u.z), a4);  a5 = fmaf(wv, hi_bf(u.z), a5);
        a6 = fmaf(wv, lo_bf(u.w), a6);  a7 = fmaf(wv, hi_bf(u.w), a7);
    }
    uint4 o;
    o.x = pack_bf2(a0, a1);  o.y = pack_bf2(a2, a3);
    o.z = pack_bf2(a4, a5);  o.w = pack_bf2(a6, a7);
    ((uint4*)(g_bf + out_off))[s * 128 + t] = o;
}

// Per-batch-column max over S rows (bf16 source). grid (4 b-tiles, 32 s-chunks).
__global__ void __launch_bounds__(256) k_max(unsigned s_off, int rows_per) {
    int b = (blockIdx.x << 8) + threadIdx.x;
    const unsigned short* sr =
        (const unsigned short*)g_bf + s_off + (unsigned)blockIdx.y * rows_per * BATCH + b;
    float loc = 0.0f;
#pragma unroll 8
    for (int i = 0; i < rows_per; i++)
        loc = fmaxf(loc, __uint_as_float((unsigned)sr[i * BATCH] << 16));
    atomicMax(reinterpret_cast<int*>(g_m + b), __float_as_int(loc));
}

// Root: fused layer-4 prod + root sum. Only the 32 referenced elements are
// computed: acc = sum_c w4_c * s3[p0_c]*s3[p1_c];  out = log(acc) + 4*log m2.
__global__ void __launch_bounds__(256) k_root(float* __restrict__ out,
                                              const int* __restrict__ cids,
                                              const int* __restrict__ pids,
                                              const float* __restrict__ w) {
    __shared__ float sw[32];
    __shared__ int   sp0[32], sp1[32];
    int t = threadIdx.x;
    if (t < 32) {
        float wv = w[t];
        float mx = wv;
#pragma unroll
        for (int o = 16; o; o >>= 1) mx = fmaxf(mx, __shfl_xor_sync(0xffffffffu, mx, o));
        float e = __expf(wv - mx);
        float sm = e;
#pragma unroll
        for (int o = 16; o; o >>= 1) sm += __shfl_xor_sync(0xffffffffu, sm, o);
        sw[t] = e * __frcp_rn(sm);
        int elem = cids[t] - 1;                    // pids4 row of this element
        const int start4 = 1 + 8192 + 4096 + 2048; // s3 global-id base
        sp0[t] = __ldg(&pids[elem * 2])     - start4;
        sp1[t] = __ldg(&pids[elem * 2 + 1]) - start4;
    }
    __syncthreads();
    const uint2* s3 = (const uint2*)(g_bf + S3O);
    float a0 = 0.f, a1 = 0.f, a2 = 0.f, a3 = 0.f;
#pragma unroll
    for (int c = 0; c < 32; c++) {
        uint2 u0 = s3[(unsigned)sp0[c] * 256 + t];
        uint2 u1 = s3[(unsigned)sp1[c] * 256 + t];
        float wv = sw[c];
        a0 = fmaf(wv, lo_bf(u0.x) * lo_bf(u1.x), a0);
        a1 = fmaf(wv, hi_bf(u0.x) * hi_bf(u1.x), a1);
        a2 = fmaf(wv, lo_bf(u0.y) * lo_bf(u1.y), a2);
        a3 = fmaf(wv, hi_bf(u0.y) * hi_bf(u1.y), a3);
    }
    const float4* m2 = (const float4*)g_m;
    float4 b2 = m2[t];
    float4 o;
    o.x = logf(a0) + 4.f * logf(b2.x);
    o.y = logf(a1) + 4.f * logf(b2.y);
    o.z = logf(a2) + 4.f * logf(b2.z);
    o.w = logf(a3) + 4.f * logf(b2.w);
    ((float4*)out)[t] = o;
}

extern "C" void kernel_launch(void* const* d_in, const int* in_sizes, int n_in,
                              void* d_out, int out_size) {
    const int*   x      = (const int*)d_in[0];
    const float* logits = (const float*)d_in[1];
    const float* w1     = (const float*)d_in[2];
    const float* w2     = (const float*)d_in[3];
    const float* w3     = (const float*)d_in[4];
    const float* w4     = (const float*)d_in[5];
    const int*   pids1  = (const int*)d_in[6];
    const int*   pids2  = (const int*)d_in[7];
    const int*   pids3  = (const int*)d_in[8];
    const int*   pids4  = (const int*)d_in[9];
    const int*   cids1  = (const int*)d_in[10];
    const int*   cids2  = (const int*)d_in[11];
    const int*   cids3  = (const int*)d_in[12];
    const int*   cids4  = (const int*)d_in[13];

    k_inp<<<NV, 256>>>(logits, x);             // fused softmax+gather, zeros g_m

    // Layer 1: prod from inputs (global ids start at 1).
    k_prod<<<8192 / EPB, 256>>>(EMO, LIN0, pids1, 1, 0);
    k_sum<<<4096, 128>>>(S1O, EMO, cids1, w1);

    // Layer 2: prod from s1 (ids start 8193). s1 range safe in bf16 -> no renorm.
    k_prod<<<4096 / EPB, 256>>>(EMO, S1O, pids2, 1 + 8192, 0);
    k_sum<<<2048, 128>>>(S2O, EMO, cids2, w2);
    k_max<<<dim3(4, 32), 256>>>(S2O, 2048 / 32);

    // Layer 3: prod from s2 (ids start 12289), renormalize by m2.
    k_prod<<<2048 / EPB, 256>>>(EMO, S2O, pids3, 1 + 8192 + 4096, 1);
    k_sum<<<1024, 128>>>(S3O, EMO, cids3, w3);

    // Layer 4 (prod+sum) fused into the root kernel.
    k_root<<<1, 256>>>((float*)d_out, cids4, pids4, w4);
}

// round 10
// speedup vs baseline: 1.8879x; 1.0956x over previous
#include <cuda_runtime.h>
#include <cuda_bf16.h>

// ---------------------------------------------------------------------------
// TensorCircuit forward, linear domain, bf16 activation storage.
//   input:  lin0[i,b] = softmax(in_logits[i])[x[b, i/32]]         (bf16)
//   prod l: em[e,b]   = prev[p0,b]*prev[p1,b] (/ m2^2 at layer 3) (bf16)
//   sum  l: s[s,b]    = sum_c softmax(w[s])[c] * em[cid,b]        (bf16, fp32 acc)
//   renorm: single per-batch-column max m2 after s2
//   layer4 prod+sum collapsed into k_root (only 32 of 1024 elements used).
//   root   = log( sum_c w4_c * s3[p0_c]*s3[p1_c] ) + 4*log m2     (fp32)
// ---------------------------------------------------------------------------

#define BATCH 1024
#define NV    256
#define NK    64
#define NM    32
#define NN0   8192

// bf16 arena (element offsets). All offsets are multiples of 1024 -> 16B aligned.
#define LIN0  0u
#define EMO   (8192u * 1024u)
#define S1O   (EMO + 8192u * 1024u)
#define S2O   (S1O + 4096u * 1024u)
#define S3O   (S2O + 2048u * 1024u)
#define BF_SZ (S3O + 1024u * 1024u)

__device__ __nv_bfloat16 g_bf[BF_SZ];
__device__ float g_m[BATCH];        // per-column renorm max m2 (fp32)

// --- bf16 bit-trick helpers -------------------------------------------------
__device__ __forceinline__ float lo_bf(unsigned u) { return __uint_as_float(u << 16); }
__device__ __forceinline__ float hi_bf(unsigned u) { return __uint_as_float(u & 0xffff0000u); }
__device__ __forceinline__ unsigned pack_bf2(float lo, float hi) {
    unsigned r;
    asm("cvt.rn.bf16x2.f32 %0, %1, %2;" : "=r"(r) : "f"(hi), "f"(lo));
    return r;
}

// Fused input layer: per-variable block computes the 32-row softmax tile in
// smem (transposed, padded), then each thread gathers for a COLUMN PAIR and
// writes packed bf16x2 -> full 128B store wavefronts. Blocks 0..3 zero g_m.
__global__ void __launch_bounds__(256) k_inp(const float* __restrict__ L,
                                             const int* __restrict__ x) {
    __shared__ float Pt[NK][NM + 1];   // transposed softmax tile, padded
    int v = blockIdx.x;
    if (v < 4) g_m[v * 256 + threadIdx.x] = 0.0f;
    int warp = threadIdx.x >> 5, lane = threadIdx.x & 31;
    // 8 warps x 4 rows each: softmax over 64 logits per row.
#pragma unroll
    for (int i = 0; i < 4; i++) {
        int m = warp * 4 + i;
        const float* lr = L + (v * NM + m) * NK;
        float v0 = lr[lane], v1 = lr[lane + 32];
        float mx = fmaxf(v0, v1);
#pragma unroll
        for (int o = 16; o; o >>= 1) mx = fmaxf(mx, __shfl_xor_sync(0xffffffffu, mx, o));
        float e0 = __expf(v0 - mx), e1 = __expf(v1 - mx);
        float sm = e0 + e1;
#pragma unroll
        for (int o = 16; o; o >>= 1) sm += __shfl_xor_sync(0xffffffffu, sm, o);
        float inv = __frcp_rn(sm);
        Pt[lane][m]      = e0 * inv;
        Pt[lane + 32][m] = e1 * inv;
    }
    __syncthreads();
#pragma unroll
    for (int j = 0; j < 2; j++) {
        int b = (threadIdx.x + j * 256) * 2;          // columns b, b+1
        int i0 = x[b * NV + v];
        int i1 = x[(b + 1) * NV + v];
        unsigned* o = (unsigned*)((unsigned short*)(g_bf + LIN0)
                                  + (unsigned)(v * NM) * BATCH + b);
#pragma unroll
        for (int m = 0; m < NM; m++)
            o[m * (BATCH / 2)] = pack_bf2(Pt[i0][m], Pt[i1][m]);
    }
}

// Prod layer: em[e,b] = prev[p0,b]*prev[p1,b] (* 1/m2^2 when renormalizing).
// 256 threads = 2 half-blocks of 128; each half handles 2 elements, fully
// unrolled: all 4 pid loads then all 4 row loads issued back-to-back.
// grid = E/4.
__global__ void __launch_bounds__(256) k_prod(unsigned em_off, unsigned prev_off,
                                              const int* __restrict__ pids, int start,
                                              int use_m) {
    int tid = threadIdx.x;
    int half = tid >> 7, t = tid & 127;
    unsigned e0 = blockIdx.x * 4 + half;              // this half's elements: e0, e0+2
    const int* pp = pids + e0 * 2;
    int p00 = __ldg(pp)     - start;
    int p01 = __ldg(pp + 1) - start;
    int p10 = __ldg(pp + 4) - start;
    int p11 = __ldg(pp + 5) - start;
    const uint4* prev = (const uint4*)(g_bf + prev_off);
    uint4 ua0 = prev[(unsigned)p00 * 128 + t];
    uint4 ub0 = prev[(unsigned)p01 * 128 + t];
    uint4 ua1 = prev[(unsigned)p10 * 128 + t];
    uint4 ub1 = prev[(unsigned)p11 * 128 + t];
    float inv[8];
    if (use_m) {
        const float4* mm = (const float4*)g_m;
        float4 m0 = mm[2 * t], m1 = mm[2 * t + 1];
        inv[0] = __frcp_rn(m0.x * m0.x);  inv[1] = __frcp_rn(m0.y * m0.y);
        inv[2] = __frcp_rn(m0.z * m0.z);  inv[3] = __frcp_rn(m0.w * m0.w);
        inv[4] = __frcp_rn(m1.x * m1.x);  inv[5] = __frcp_rn(m1.y * m1.y);
        inv[6] = __frcp_rn(m1.z * m1.z);  inv[7] = __frcp_rn(m1.w * m1.w);
    }
    float r0[8], r1[8];
    r0[0] = lo_bf(ua0.x) * lo_bf(ub0.x);  r0[1] = hi_bf(ua0.x) * hi_bf(ub0.x);
    r0[2] = lo_bf(ua0.y) * lo_bf(ub0.y);  r0[3] = hi_bf(ua0.y) * hi_bf(ub0.y);
    r0[4] = lo_bf(ua0.z) * lo_bf(ub0.z);  r0[5] = hi_bf(ua0.z) * hi_bf(ub0.z);
    r0[6] = lo_bf(ua0.w) * lo_bf(ub0.w);  r0[7] = hi_bf(ua0.w) * hi_bf(ub0.w);
    r1[0] = lo_bf(ua1.x) * lo_bf(ub1.x);  r1[1] = hi_bf(ua1.x) * hi_bf(ub1.x);
    r1[2] = lo_bf(ua1.y) * lo_bf(ub1.y);  r1[3] = hi_bf(ua1.y) * hi_bf(ub1.y);
    r1[4] = lo_bf(ua1.z) * lo_bf(ub1.z);  r1[5] = hi_bf(ua1.z) * hi_bf(ub1.z);
    r1[6] = lo_bf(ua1.w) * lo_bf(ub1.w);  r1[7] = hi_bf(ua1.w) * hi_bf(ub1.w);
    if (use_m) {
#pragma unroll
        for (int j = 0; j < 8; j++) { r0[j] *= inv[j]; r1[j] *= inv[j]; }
    }
    uint4* out = (uint4*)(g_bf + em_off);
    uint4 o0, o1;
    o0.x = pack_bf2(r0[0], r0[1]);  o0.y = pack_bf2(r0[2], r0[3]);
    o0.z = pack_bf2(r0[4], r0[5]);  o0.w = pack_bf2(r0[6], r0[7]);
    o1.x = pack_bf2(r1[0], r1[1]);  o1.y = pack_bf2(r1[2], r1[3]);
    o1.z = pack_bf2(r1[4], r1[5]);  o1.w = pack_bf2(r1[6], r1[7]);
    out[e0 * 128 + t]       = o0;
    out[(e0 + 2) * 128 + t] = o1;
}

// Sum layer: out[s,b] = sum_c softmax(w[s])[c] * em[cids[s,c]-1, b].
// One block per sum node; 128 threads x 8 bf16 cover the batch. fp32 acc.
__global__ void __launch_bounds__(128) k_sum(unsigned out_off, unsigned em_off,
                                             const int* __restrict__ cids,
                                             const float* __restrict__ w) {
    __shared__ uint2 swc[32];
    int s = blockIdx.x, t = threadIdx.x;
    if (t < 32) {
        float wv = w[s * 32 + t];
        float mx = wv;
#pragma unroll
        for (int o = 16; o; o >>= 1) mx = fmaxf(mx, __shfl_xor_sync(0xffffffffu, mx, o));
        float e = __expf(wv - mx);
        float sm = e;
#pragma unroll
        for (int o = 16; o; o >>= 1) sm += __shfl_xor_sync(0xffffffffu, sm, o);
        unsigned off = (unsigned)(cids[s * 32 + t] - 1) * 2048u;  // byte offset of row
        swc[t] = make_uint2(__float_as_uint(e * __frcp_rn(sm)), off);
    }
    __syncthreads();
    const char* base = (const char*)(g_bf + em_off) + t * 16;
    float a0 = 0.f, a1 = 0.f, a2 = 0.f, a3 = 0.f;
    float a4 = 0.f, a5 = 0.f, a6 = 0.f, a7 = 0.f;
#pragma unroll
    for (int c = 0; c < 32; c++) {
        uint2 wc = swc[c];
        uint4 u = *(const uint4*)(base + wc.y);
        float wv = __uint_as_float(wc.x);
        a0 = fmaf(wv, lo_bf(u.x), a0);  a1 = fmaf(wv, hi_bf(u.x), a1);
        a2 = fmaf(wv, lo_bf(u.y), a2);  a3 = fmaf(wv, hi_bf(u.y), a3);
        a4 = fmaf(wv, lo_bf(u.z), a4);  a5 = fmaf(wv, hi_bf(u.z), a5);
        a6 = fmaf(wv, lo_bf(u.w), a6);  a7 = fmaf(wv, hi_bf(u.w), a7);
    }
    uint4 o;
    o.x = pack_bf2(a0, a1);  o.y = pack_bf2(a2, a3);
    o.z = pack_bf2(a4, a5);  o.w = pack_bf2(a6, a7);
    ((uint4*)(g_bf + out_off))[s * 128 + t] = o;
}

// Per-batch-column max over S rows (bf16 source). grid (4 b-tiles, 32 s-chunks).
__global__ void __launch_bounds__(256) k_max(unsigned s_off, int rows_per) {
    int b = (blockIdx.x << 8) + threadIdx.x;
    const unsigned short* sr =
        (const unsigned short*)g_bf + s_off + (unsigned)blockIdx.y * rows_per * BATCH + b;
    float loc = 0.0f;
#pragma unroll 8
    for (int i = 0; i < rows_per; i++)
        loc = fmaxf(loc, __uint_as_float((unsigned)sr[i * BATCH] << 16));
    atomicMax(reinterpret_cast<int*>(g_m + b), __float_as_int(loc));
}

// Root: fused layer-4 prod + root sum. Only the 32 referenced elements are
// computed: acc = sum_c w4_c * s3[p0_c]*s3[p1_c];  out = log(acc) + 4*log m2.
__global__ void __launch_bounds__(256) k_root(float* __restrict__ out,
                                              const int* __restrict__ cids,
                                              const int* __restrict__ pids,
                                              const float* __restrict__ w) {
    __shared__ float sw[32];
    __shared__ int   sp0[32], sp1[32];
    int t = threadIdx.x;
    if (t < 32) {
        float wv = w[t];
        float mx = wv;
#pragma unroll
        for (int o = 16; o; o >>= 1) mx = fmaxf(mx, __shfl_xor_sync(0xffffffffu, mx, o));
        float e = __expf(wv - mx);
        float sm = e;
#pragma unroll
        for (int o = 16; o; o >>= 1) sm += __shfl_xor_sync(0xffffffffu, sm, o);
        sw[t] = e * __frcp_rn(sm);
        int elem = cids[t] - 1;                    // pids4 row of this element
        const int start4 = 1 + 8192 + 4096 + 2048; // s3 global-id base
        sp0[t] = __ldg(&pids[elem * 2])     - start4;
        sp1[t] = __ldg(&pids[elem * 2 + 1]) - start4;
    }
    __syncthreads();
    const uint2* s3 = (const uint2*)(g_bf + S3O);
    float a0 = 0.f, a1 = 0.f, a2 = 0.f, a3 = 0.f;
#pragma unroll
    for (int c = 0; c < 32; c++) {
        uint2 u0 = s3[(unsigned)sp0[c] * 256 + t];
        uint2 u1 = s3[(unsigned)sp1[c] * 256 + t];
        float wv = sw[c];
        a0 = fmaf(wv, lo_bf(u0.x) * lo_bf(u1.x), a0);
        a1 = fmaf(wv, hi_bf(u0.x) * hi_bf(u1.x), a1);
        a2 = fmaf(wv, lo_bf(u0.y) * lo_bf(u1.y), a2);
        a3 = fmaf(wv, hi_bf(u0.y) * hi_bf(u1.y), a3);
    }
    const float4* m2 = (const float4*)g_m;
    float4 b2 = m2[t];
    float4 o;
    o.x = logf(a0) + 4.f * logf(b2.x);
    o.y = logf(a1) + 4.f * logf(b2.y);
    o.z = logf(a2) + 4.f * logf(b2.z);
    o.w = logf(a3) + 4.f * logf(b2.w);
    ((float4*)out)[t] = o;
}

extern "C" void kernel_launch(void* const* d_in, const int* in_sizes, int n_in,
                              void* d_out, int out_size) {
    const int*   x      = (const int*)d_in[0];
    const float* logits = (const float*)d_in[1];
    const float* w1     = (const float*)d_in[2];
    const float* w2     = (const float*)d_in[3];
    const float* w3     = (const float*)d_in[4];
    const float* w4     = (const float*)d_in[5];
    const int*   pids1  = (const int*)d_in[6];
    const int*   pids2  = (const int*)d_in[7];
    const int*   pids3  = (const int*)d_in[8];
    const int*   pids4  = (const int*)d_in[9];
    const int*   cids1  = (const int*)d_in[10];
    const int*   cids2  = (const int*)d_in[11];
    const int*   cids3  = (const int*)d_in[12];
    const int*   cids4  = (const int*)d_in[13];

    k_inp<<<NV, 256>>>(logits, x);             // fused softmax+gather, zeros g_m

    // Layer 1: prod from inputs (global ids start at 1).
    k_prod<<<8192 / 4, 256>>>(EMO, LIN0, pids1, 1, 0);
    k_sum<<<4096, 128>>>(S1O, EMO, cids1, w1);

    // Layer 2: prod from s1 (ids start 8193). s1 range safe in bf16 -> no renorm.
    k_prod<<<4096 / 4, 256>>>(EMO, S1O, pids2, 1 + 8192, 0);
    k_sum<<<2048, 128>>>(S2O, EMO, cids2, w2);
    k_max<<<dim3(4, 32), 256>>>(S2O, 2048 / 32);

    // Layer 3: prod from s2 (ids start 12289), renormalize by m2.
    k_prod<<<2048 / 4, 256>>>(EMO, S2O, pids3, 1 + 8192 + 4096, 1);
    k_sum<<<1024, 128>>>(S3O, EMO, cids3, w3);

    // Layer 4 (prod+sum) fused into the root kernel.
    k_root<<<1, 256>>>((float*)d_out, cids4, pids4, w4);
}